// round 1
// baseline (speedup 1.0000x reference)
#include <cuda_runtime.h>
#include <math.h>

// Problem constants (fixed by the dataset)
#define BATCH   512
#define IN_DIM  128
#define OUT_DIM 128
#define NFEAT   9                 // silu + 8 basis functions
#define KTOT    (IN_DIM * NFEAT)  // 1152
#define SPLITS  8                 // split-K over i: 16 i's per split
#define KC      (KTOT / SPLITS)   // 144 k per split
#define CHUNK   48                // smem k-chunk (144 = 3 * 48)
#define BM      32                // batch rows per GEMM block

// Scratch (device globals — no allocation in kernel_launch)
__device__ float g_F[KTOT * BATCH];            // featurized inputs, [k][n]
__device__ float g_W[KTOT * OUT_DIM];          // weights,            [k][o]
__device__ float g_P[SPLITS * BATCH * OUT_DIM];// split-K partials

// ---------------------------------------------------------------------------
// Prep: featurize x (silu + cubic B-spline basis, shared knot vector) and
// build the weight matrix from coef/scales/mask. 65536 threads.
// ---------------------------------------------------------------------------
__global__ void prep_kernel(const float* __restrict__ x,
                            const float* __restrict__ grid,
                            const float* __restrict__ coef,
                            const float* __restrict__ sb,
                            const float* __restrict__ ss,
                            const float* __restrict__ mask) {
    const int t = blockIdx.x * blockDim.x + threadIdx.x;

    // Extended knot vector (row 0 of grid; all rows identical in this problem).
    // Matches extend_knots_uniform exactly in fp32.
    float g0 = grid[0];
    float g5 = grid[5];
    float step = (g5 - g0) / 5.0f;
    float tk[12];
    tk[0]  = g0 - step * 3.0f;
    tk[1]  = g0 - step * 2.0f;
    tk[2]  = g0 - step;
    tk[3]  = g0;
    tk[4]  = grid[1];
    tk[5]  = grid[2];
    tk[6]  = grid[3];
    tk[7]  = grid[4];
    tk[8]  = g5;
    tk[9]  = g5 + step;
    tk[10] = g5 + step * 2.0f;
    tk[11] = g5 + step * 3.0f;

    // ---- featurize: thread t -> (n = t & 511, i = t >> 9) ----
    {
        const int n = t & (BATCH - 1);
        const int i = t >> 9;
        const float xv = x[n * IN_DIM + i];

        // silu
        const float sig  = 1.0f / (1.0f + expf(-xv));
        const float silu = xv * sig;

        // Cox-de Boor, order K=3, matching reference fp32 arithmetic
        float B[11];
#pragma unroll
        for (int m = 0; m < 11; m++)
            B[m] = (xv >= tk[m] && xv < tk[m + 1]) ? 1.0f : 0.0f;

#pragma unroll
        for (int r = 1; r <= 3; r++) {
#pragma unroll
            for (int m = 0; m < 11 - r; m++) {
                float da = fmaxf(tk[m + r] - tk[m], 1e-14f);
                float db = fmaxf(tk[m + r + 1] - tk[m + 1], 1e-14f);
                float alpha = (xv - tk[m]) / da;
                float beta  = (tk[m + r + 1] - xv) / db;
                B[m] = alpha * B[m] + beta * B[m + 1];
            }
        }

        const int kb = i * NFEAT;
        g_F[(kb + 0) * BATCH + n] = silu;   // coalesced: warp = consecutive n
#pragma unroll
        for (int j = 0; j < 8; j++)
            g_F[(kb + 1 + j) * BATCH + n] = B[j];
    }

    // ---- build W: thread t = s for t < 16384 ----
    if (t < IN_DIM * OUT_DIM) {
        const int s = t;
        const int o = s >> 7;       // s / IN_DIM
        const int i = s & 127;      // s % IN_DIM
        const float mk = mask[s];
        const float wb = mk * sb[s];
        const float ws = mk * ss[s];
        const int kb = i * NFEAT;
        g_W[kb * OUT_DIM + o] = wb;
#pragma unroll
        for (int j = 0; j < 8; j++)
            g_W[(kb + 1 + j) * OUT_DIM + o] = ws * coef[s * 8 + j];
    }
}

// ---------------------------------------------------------------------------
// Split-K SGEMM: out_partial[split][n][o] = sum over k-chunk of F[k][n]*W[k][o]
// grid = (BATCH/BM = 16, SPLITS = 8) = 128 blocks; 256 threads; 4x4 reg tile.
// ---------------------------------------------------------------------------
__global__ void __launch_bounds__(256, 1) gemm_kernel() {
    __shared__ float Fs[CHUNK][BM];        // 6.0 KB
    __shared__ float Ws[CHUNK][OUT_DIM];   // 24.0 KB

    const int m0 = blockIdx.x * BM;
    const int k0 = blockIdx.y * KC;
    const int t  = threadIdx.x;
    const int tm = t >> 5;                 // 0..7  : m-tile (rows tm*4..tm*4+3)
    const int to = t & 31;                 // 0..31 : o-tile (cols to*4..to*4+3)

    float acc[4][4] = {};

#pragma unroll
    for (int c = 0; c < KC / CHUNK; c++) {
        const int kb = k0 + c * CHUNK;
        __syncthreads();
        // load Ws: 48*128 = 6144 floats, 24 per thread, fully coalesced
#pragma unroll
        for (int q = 0; q < (CHUNK * OUT_DIM) / 256; q++) {
            int p = t + 256 * q;
            Ws[p >> 7][p & 127] = g_W[(kb + (p >> 7)) * OUT_DIM + (p & 127)];
        }
        // load Fs: 48*32 = 1536 floats, 6 per thread
#pragma unroll
        for (int q = 0; q < (CHUNK * BM) / 256; q++) {
            int p = t + 256 * q;
            Fs[p >> 5][p & 31] = g_F[(kb + (p >> 5)) * BATCH + m0 + (p & 31)];
        }
        __syncthreads();

#pragma unroll 8
        for (int kk = 0; kk < CHUNK; kk++) {
            const float4 f = *(const float4*)&Fs[kk][tm * 4]; // broadcast in warp
            const float4 w = *(const float4*)&Ws[kk][to * 4];
            acc[0][0] += f.x * w.x; acc[0][1] += f.x * w.y;
            acc[0][2] += f.x * w.z; acc[0][3] += f.x * w.w;
            acc[1][0] += f.y * w.x; acc[1][1] += f.y * w.y;
            acc[1][2] += f.y * w.z; acc[1][3] += f.y * w.w;
            acc[2][0] += f.z * w.x; acc[2][1] += f.z * w.y;
            acc[2][2] += f.z * w.z; acc[2][3] += f.z * w.w;
            acc[3][0] += f.w * w.x; acc[3][1] += f.w * w.y;
            acc[3][2] += f.w * w.z; acc[3][3] += f.w * w.w;
        }
    }

    float* P = &g_P[blockIdx.y * (BATCH * OUT_DIM)];
#pragma unroll
    for (int im = 0; im < 4; im++) {
        const int row = m0 + tm * 4 + im;
        float4 v = make_float4(acc[im][0], acc[im][1], acc[im][2], acc[im][3]);
        *(float4*)&P[row * OUT_DIM + to * 4] = v;
    }
}

// ---------------------------------------------------------------------------
// Reduce: sum the 8 split-K partials into the final output (deterministic).
// ---------------------------------------------------------------------------
__global__ void reduce_kernel(float* __restrict__ out) {
    const int t = blockIdx.x * blockDim.x + threadIdx.x;
    float s = 0.0f;
#pragma unroll
    for (int q = 0; q < SPLITS; q++)
        s += g_P[q * (BATCH * OUT_DIM) + t];
    out[t] = s;
}

// ---------------------------------------------------------------------------
extern "C" void kernel_launch(void* const* d_in, const int* in_sizes, int n_in,
                              void* d_out, int out_size) {
    const float* x    = (const float*)d_in[0];
    const float* grid = (const float*)d_in[1];
    const float* coef = (const float*)d_in[2];
    const float* sb   = (const float*)d_in[3];
    const float* ss   = (const float*)d_in[4];
    const float* mask = (const float*)d_in[5];
    float* out = (float*)d_out;

    prep_kernel<<<256, 256>>>(x, grid, coef, sb, ss, mask);   // 65536 threads
    gemm_kernel<<<dim3(BATCH / BM, SPLITS), 256>>>();          // 128 blocks
    reduce_kernel<<<256, 256>>>(out);                          // 65536 threads
}

// round 2
// speedup vs baseline: 1.1045x; 1.1045x over previous
#include <cuda_runtime.h>
#include <math.h>

// Problem constants (fixed by the dataset)
#define BATCH   512
#define IN_DIM  128
#define OUT_DIM 128
#define NFEAT   9                 // silu + 8 basis functions
#define KTOT    (IN_DIM * NFEAT)  // 1152
#define SPLITS  18                // split-K: KC = 64
#define KC      (KTOT / SPLITS)   // 64
#define BM      64                // batch rows per GEMM block

// Scratch (device globals — no allocation in kernel_launch)
__device__ float g_F[KTOT * BATCH];             // featurized inputs, [k][n]
__device__ float g_W[KTOT * OUT_DIM];           // weights,           [k][o]
__device__ float g_P[SPLITS * BATCH * OUT_DIM]; // split-K partials

// ---------------------------------------------------------------------------
// f32x2 packed helpers (sm_103a FFMA2 — ptxas never emits this from C++)
// ---------------------------------------------------------------------------
__device__ __forceinline__ unsigned long long dup_f32x2(float v) {
    unsigned long long d;
    unsigned int u = __float_as_uint(v);
    asm("mov.b64 %0, {%1, %1};" : "=l"(d) : "r"(u));
    return d;
}
__device__ __forceinline__ void ffma2(unsigned long long& acc,
                                      unsigned long long a,
                                      unsigned long long b) {
    asm("fma.rn.f32x2 %0, %1, %2, %0;" : "+l"(acc) : "l"(a), "l"(b));
}

// ---------------------------------------------------------------------------
// Prep: featurize x (silu + cubic B-spline basis) and build weights.
// Division-free: uniform knots => denominators are exactly r*step.
// ---------------------------------------------------------------------------
__global__ void prep_kernel(const float* __restrict__ x,
                            const float* __restrict__ grid,
                            const float* __restrict__ coef,
                            const float* __restrict__ sb,
                            const float* __restrict__ ss,
                            const float* __restrict__ mask) {
    const int t = blockIdx.x * blockDim.x + threadIdx.x;

    const float g0 = grid[0];
    const float g5 = grid[5];
    const float step = (g5 - g0) * 0.2f;
    const float inv1 = __frcp_rn(step);
    const float inv2 = 0.5f * inv1;
    const float inv3 = inv1 * (1.0f / 3.0f);

    float tk[12];
    tk[0]  = g0 - step * 3.0f;
    tk[1]  = g0 - step * 2.0f;
    tk[2]  = g0 - step;
    tk[3]  = g0;
    tk[4]  = grid[1];
    tk[5]  = grid[2];
    tk[6]  = grid[3];
    tk[7]  = grid[4];
    tk[8]  = g5;
    tk[9]  = g5 + step;
    tk[10] = g5 + step * 2.0f;
    tk[11] = g5 + step * 3.0f;

    // ---- featurize: thread t -> (n = t & 511, i = t >> 9) ----
    {
        const int n = t & (BATCH - 1);
        const int i = t >> 9;
        const float xv = __ldg(&x[n * IN_DIM + i]);

        const float sig  = __frcp_rn(1.0f + __expf(-xv));
        const float silu = xv * sig;

        float B[11];
#pragma unroll
        for (int m = 0; m < 11; m++)
            B[m] = (xv >= tk[m] && xv < tk[m + 1]) ? 1.0f : 0.0f;

        const float invr[3] = {inv1, inv2, inv3};
#pragma unroll
        for (int r = 1; r <= 3; r++) {
            const float iv = invr[r - 1];
#pragma unroll
            for (int m = 0; m < 11 - r; m++) {
                float alpha = (xv - tk[m]) * iv;
                float beta  = (tk[m + r + 1] - xv) * iv;
                B[m] = alpha * B[m] + beta * B[m + 1];
            }
        }

        const int kb = i * NFEAT;
        g_F[(kb + 0) * BATCH + n] = silu;   // coalesced: warp = consecutive n
#pragma unroll
        for (int j = 0; j < 8; j++)
            g_F[(kb + 1 + j) * BATCH + n] = B[j];
    }

    // ---- build W: thread t = s for t < 16384 ----
    if (t < IN_DIM * OUT_DIM) {
        const int s = t;
        const int o = s >> 7;
        const int i = s & 127;
        const float mk = mask[s];
        const float wb = mk * sb[s];
        const float ws = mk * ss[s];
        const int kb = i * NFEAT;
        g_W[kb * OUT_DIM + o] = wb;
#pragma unroll
        for (int j = 0; j < 8; j++)
            g_W[(kb + 1 + j) * OUT_DIM + o] = ws * coef[s * 8 + j];
    }
}

// ---------------------------------------------------------------------------
// Split-K SGEMM with packed f32x2 FMAs.
// grid = (8 M-tiles, 18 K-splits) = 144 blocks; 128 threads; 8x8 reg tile.
// Block tile: 64m x 128o x 64k. Smem: Fs 16KB + Ws 32KB = 48KB, loaded once.
// ---------------------------------------------------------------------------
__global__ void __launch_bounds__(128, 1) gemm_kernel() {
    __shared__ float Fs[KC * BM];       // [k][m], 16 KB
    __shared__ float Ws[KC * OUT_DIM];  // [k][o], 32 KB

    const int m0 = blockIdx.x * BM;
    const int k0 = blockIdx.y * KC;
    const int t  = threadIdx.x;
    const int tm8 = (t >> 4) * 8;       // 0..56 : 8 m-rows
    const int to8 = (t & 15) * 8;       // 0..120: 8 o-cols

    // Fill Ws: contiguous 8192 floats from g_W + k0*128
    {
        const float4* src = (const float4*)&g_W[k0 * OUT_DIM];
        float4* dst = (float4*)Ws;
#pragma unroll
        for (int q = 0; q < (KC * OUT_DIM) / (128 * 4); q++)
            dst[t + 128 * q] = src[t + 128 * q];
    }
    // Fill Fs: 64 rows of 64 floats from stride-512 g_F
#pragma unroll
    for (int q = 0; q < (KC * BM) / (128 * 4); q++) {
        int p = t + 128 * q;             // float4 index
        int row = p >> 4;
        int c4  = p & 15;
        ((float4*)Fs)[p] = *(const float4*)&g_F[(k0 + row) * BATCH + m0 + c4 * 4];
    }
    __syncthreads();

    unsigned long long acc[8][4];        // 8 m-rows x 4 o-pairs
#pragma unroll
    for (int a = 0; a < 8; a++)
#pragma unroll
        for (int b = 0; b < 4; b++) acc[a][b] = 0ULL;

#pragma unroll 4
    for (int k = 0; k < KC; k++) {
        const float4 fa = *(const float4*)&Fs[k * BM + tm8];
        const float4 fb = *(const float4*)&Fs[k * BM + tm8 + 4];
        const ulonglong2 wa = *(const ulonglong2*)&Ws[k * OUT_DIM + to8];
        const ulonglong2 wb = *(const ulonglong2*)&Ws[k * OUT_DIM + to8 + 4];

        unsigned long long fd[8];
        fd[0] = dup_f32x2(fa.x); fd[1] = dup_f32x2(fa.y);
        fd[2] = dup_f32x2(fa.z); fd[3] = dup_f32x2(fa.w);
        fd[4] = dup_f32x2(fb.x); fd[5] = dup_f32x2(fb.y);
        fd[6] = dup_f32x2(fb.z); fd[7] = dup_f32x2(fb.w);

#pragma unroll
        for (int a = 0; a < 8; a++) {
            ffma2(acc[a][0], fd[a], wa.x);
            ffma2(acc[a][1], fd[a], wa.y);
            ffma2(acc[a][2], fd[a], wb.x);
            ffma2(acc[a][3], fd[a], wb.y);
        }
    }

    float* P = &g_P[blockIdx.y * (BATCH * OUT_DIM)];
#pragma unroll
    for (int a = 0; a < 8; a++) {
        const int row = m0 + tm8 + a;
        ulonglong2 v0; v0.x = acc[a][0]; v0.y = acc[a][1];
        ulonglong2 v1; v1.x = acc[a][2]; v1.y = acc[a][3];
        *(ulonglong2*)&P[row * OUT_DIM + to8]     = v0;
        *(ulonglong2*)&P[row * OUT_DIM + to8 + 4] = v1;
    }
}

// ---------------------------------------------------------------------------
// Reduce: sum the 18 split-K partials into the final output (deterministic).
// ---------------------------------------------------------------------------
__global__ void reduce_kernel(float* __restrict__ out) {
    const int t = blockIdx.x * blockDim.x + threadIdx.x;
    float s = 0.0f;
#pragma unroll
    for (int q = 0; q < SPLITS; q++)
        s += g_P[q * (BATCH * OUT_DIM) + t];
    out[t] = s;
}

// ---------------------------------------------------------------------------
extern "C" void kernel_launch(void* const* d_in, const int* in_sizes, int n_in,
                              void* d_out, int out_size) {
    const float* x    = (const float*)d_in[0];
    const float* grid = (const float*)d_in[1];
    const float* coef = (const float*)d_in[2];
    const float* sb   = (const float*)d_in[3];
    const float* ss   = (const float*)d_in[4];
    const float* mask = (const float*)d_in[5];
    float* out = (float*)d_out;

    prep_kernel<<<256, 256>>>(x, grid, coef, sb, ss, mask);   // 65536 threads
    gemm_kernel<<<dim3(BATCH / BM, SPLITS), 128>>>();          // 144 blocks
    reduce_kernel<<<256, 256>>>(out);                          // 65536 threads
}